// round 1
// baseline (speedup 1.0000x reference)
#include <cuda_runtime.h>

#define H     4096
#define K     32
#define WO    4065          // H - K + 1
#define HPAD  4096          // padded row stride of scratch
#define RCHUNK 64

// 67 MB scratch: row-pass output, rows y in [0,4096), cols x' in [0,4065)
__device__ float g_tmp[(size_t)H * HPAD];

// skewed shared index: stride-16 per-thread bases -> lane stride 17 (conflict-free)
__device__ __forceinline__ int sk(int x) { return x + (x >> 4); }

// ---------------------------------------------------------------------------
// Pass 1: per row y, compute dist[x] = (img[y%32][x%32]-som)^2/(var+eps)
// then 1D box-sum of width K along x. One block per row.
// ---------------------------------------------------------------------------
__global__ void __launch_bounds__(256, 8)
row_pass(const float* __restrict__ img,
         const float* __restrict__ som,
         const float* __restrict__ var)
{
    __shared__ float d[H + H / 16];   // 4352 floats, skew-indexed
    __shared__ float irow[K];

    const int y = blockIdx.x;
    const int t = threadIdx.x;

    if (t < K) irow[t] = img[(y & (K - 1)) * K + t];
    __syncthreads();

    const float* srow = som + (size_t)y * H;
    const float* vrow = var + (size_t)y * H;

#pragma unroll
    for (int k = 0; k < H / 256; k++) {
        int x = t + k * 256;
        float diff = irow[x & 31] - srow[x];
        d[sk(x)] = __fdividef(diff * diff, vrow[x] + 1e-8f);
    }
    __syncthreads();

    // per-thread sliding window over 16 consecutive outputs
    const int base = t * 16;
    const int jmax = (base < WO) ? min(16, WO - base) : 0;
    float res[16];

    if (jmax > 0) {
        float s = 0.f;
#pragma unroll
        for (int i = 0; i < K; i++) s += d[sk(base + i)];
        res[0] = s;
#pragma unroll
        for (int j = 1; j < 16; j++) {
            if (j < jmax) {
                s += d[sk(base + j + K - 1)] - d[sk(base + j - 1)];
                res[j] = s;
            }
        }
    }
    __syncthreads();   // all reads of d done before overwrite

    // stage results back into shared (conflict-free: lane stride 17)
#pragma unroll
    for (int j = 0; j < 16; j++)
        if (j < jmax) d[sk(base + j)] = res[j];
    __syncthreads();

    // coalesced global store
    float* trow = g_tmp + (size_t)y * HPAD;
#pragma unroll
    for (int k = 0; k < H / 256; k++) {
        int x = t + k * 256;
        if (x < WO) trow[x] = d[sk(x)];
    }
}

// ---------------------------------------------------------------------------
// Pass 2: vertical box-sum of width K down each column of g_tmp.
// Thread = one column x', RCHUNK output rows, running sum (add top, sub bottom).
// All global accesses coalesced across the warp.
// ---------------------------------------------------------------------------
__global__ void __launch_bounds__(256)
col_pass(float* __restrict__ out)
{
    const int x = blockIdx.x * 256 + threadIdx.x;
    if (x >= WO) return;

    const int r0   = blockIdx.y * RCHUNK;
    const int rend = min(r0 + RCHUNK, WO);
    const float* col = g_tmp + x;

    float s = 0.f;
#pragma unroll
    for (int i = 0; i < K; i++)
        s += col[(size_t)(r0 + i) * HPAD];
    out[(size_t)r0 * WO + x] = s;

#pragma unroll 4
    for (int r = r0 + 1; r < rend; r++) {
        s += col[(size_t)(r + K - 1) * HPAD] - col[(size_t)(r - 1) * HPAD];
        out[(size_t)r * WO + x] = s;
    }
}

// ---------------------------------------------------------------------------
extern "C" void kernel_launch(void* const* d_in, const int* in_sizes, int n_in,
                              void* d_out, int out_size)
{
    const float* img = (const float*)d_in[0];   // [32,32]
    const float* som = (const float*)d_in[1];   // [4096,4096]
    const float* var = (const float*)d_in[2];   // [4096,4096]
    float*       out = (float*)d_out;           // [4065,4065]

    row_pass<<<H, 256>>>(img, som, var);

    dim3 grid2((WO + 255) / 256, (WO + RCHUNK - 1) / RCHUNK);
    col_pass<<<grid2, 256>>>(out);
}